// round 8
// baseline (speedup 1.0000x reference)
#include <cuda_runtime.h>
#include <cuda_bf16.h>
#include <cstdint>
#include <math.h>

// ---------------------------------------------------------------------------
// SingleHeadAttention B=4, T=2048, C=1024 fp32 — bf16-split mma.sync GEMMs
//   qkv = x @ w^T   (NT, fused epilogue -> qh/ql, kh/kl, v fp32)
//   S   = q k^T/32  (NT per batch, causal tile-skip)  -> att fp32
//   P   = softmax   -> bf16 hi/lo (register-resident, 128-aligned zero bound)
//   y   = P @ (V^T)^T (NT per batch, causal K-limit)
// GEMM: C = Ah*Bh^T + Ah*Bl^T + Al*Bh^T, fp32 accum.
// R8: CTA 128x128, 256 thr, 8 warps (2m x 4n) of 64x32.
//     kc=16 chunks, 4-stage cp.async (prefetch 3 deep), 96KB -> 2 CTAs/SM.
//     Split-term-interleaved MMA order (acc dependency spacing 4).
// ---------------------------------------------------------------------------

// ------------------------------ scratch ------------------------------------
__device__ float g_att[(size_t)4 * 2048 * 2048];
__device__ float g_vf[(size_t)4 * 2048 * 1024];
__device__ __nv_bfloat16 g_xh[(size_t)8192 * 1024];
__device__ __nv_bfloat16 g_xl[(size_t)8192 * 1024];
__device__ __nv_bfloat16 g_wh[(size_t)3072 * 1024];
__device__ __nv_bfloat16 g_wl[(size_t)3072 * 1024];
__device__ __nv_bfloat16 g_qh[(size_t)4 * 2048 * 1024];
__device__ __nv_bfloat16 g_ql[(size_t)4 * 2048 * 1024];
__device__ __nv_bfloat16 g_kh[(size_t)4 * 2048 * 1024];
__device__ __nv_bfloat16 g_kl[(size_t)4 * 2048 * 1024];
__device__ __nv_bfloat16 g_vth[(size_t)4 * 1024 * 2048];
__device__ __nv_bfloat16 g_vtl[(size_t)4 * 1024 * 2048];
__device__ __nv_bfloat16 g_ph[(size_t)4 * 2048 * 2048];
__device__ __nv_bfloat16 g_pl[(size_t)4 * 2048 * 2048];

// ------------------------------ helpers ------------------------------------
#define SA 24                                 // padded row stride (bf16), kc=16
#define TILE_B (128 * SA * 2)                 // 6144 per operand tile (128r x 16k)
#define STAGE_B (4 * TILE_B)                  // Ah, Al, Bh, Bl = 24576
#define NSTG 4
#define GEMM_SMEM (NSTG * STAGE_B)            // 98304 -> 2 CTAs/SM

__device__ __forceinline__ uint32_t smem_u32(const void* p) {
    uint32_t a;
    asm("{ .reg .u64 t; cvta.to.shared.u64 t, %1; cvt.u32.u64 %0, t; }" : "=r"(a) : "l"(p));
    return a;
}
__device__ __forceinline__ void cp16(uint32_t dst, const void* src) {
    asm volatile("cp.async.cg.shared.global [%0], [%1], 16;" :: "r"(dst), "l"(src));
}
__device__ __forceinline__ void ldmx4(uint32_t* r, uint32_t addr) {
    asm volatile("ldmatrix.sync.aligned.m8n8.x4.shared.b16 {%0,%1,%2,%3}, [%4];"
                 : "=r"(r[0]), "=r"(r[1]), "=r"(r[2]), "=r"(r[3]) : "r"(addr));
}
__device__ __forceinline__ void mma16816(float* c, const uint32_t* a, const uint32_t* b) {
    asm volatile(
        "mma.sync.aligned.m16n8k16.row.col.f32.bf16.bf16.f32 "
        "{%0,%1,%2,%3}, {%4,%5,%6,%7}, {%8,%9}, {%0,%1,%2,%3};"
        : "+f"(c[0]), "+f"(c[1]), "+f"(c[2]), "+f"(c[3])
        : "r"(a[0]), "r"(a[1]), "r"(a[2]), "r"(a[3]), "r"(b[0]), "r"(b[1]));
}
__device__ __forceinline__ uint32_t pack2bf(float v0, float v1) {
    __nv_bfloat16 h0 = __float2bfloat16(v0), h1 = __float2bfloat16(v1);
    return ((uint32_t)*(uint16_t*)&h1 << 16) | *(uint16_t*)&h0;
}

// ------------------------------ GEMM ---------------------------------------
// mode 0: C = alpha * acc (fp32);  mode 1: fused qkv split epilogue
__global__ __launch_bounds__(256, 2)
void gemm3_kernel(const __nv_bfloat16* __restrict__ Ah, const __nv_bfloat16* __restrict__ Al,
                  const __nv_bfloat16* __restrict__ Bh, const __nv_bfloat16* __restrict__ Bl,
                  float* __restrict__ C,
                  int K, int lda, int ldb, int ldc,
                  long long sAo, long long sBo, long long sCo,
                  float alpha, int causal_skip, int causal_klim, int mode, int rev_y)
{
    const int by = rev_y ? (gridDim.y - 1 - blockIdx.y) : blockIdx.y;
    const int m0 = by * 128;
    const int n0 = blockIdx.x * 128;
    if (causal_skip && n0 > m0 + 127) return;

    const int bz = blockIdx.z;
    Ah += (long long)bz * sAo;  Al += (long long)bz * sAo;
    Bh += (long long)bz * sBo;  Bl += (long long)bz * sBo;
    C  += (long long)bz * sCo;

    int Keff = K;
    if (causal_klim) { int lim = m0 + 128; Keff = (lim < K) ? lim : K; }
    const int NC = Keff / 16;                  // kc = 16

    extern __shared__ char smem[];
    const uint32_t sb = smem_u32(smem);
    const int tid = threadIdx.x;
    const int wid = tid >> 5;
    const int lane = tid & 31;

    // stage loader: 4 tiles of [128 rows x 16 bf16]; 2 x 16B chunks per row.
    // 256 ids per tile -> each thread does exactly one cp16 per tile.
    const int lrow = tid >> 1;
    const int lc16 = tid & 1;
    const uint32_t lso = (uint32_t)(lrow * SA + lc16 * 8) * 2;
    auto load_stage = [&](int s, int c) {
        const uint32_t base = sb + s * STAGE_B;
        const int k0 = c * 16;
        const long long ga = (long long)(m0 + lrow) * lda + k0 + lc16 * 8;
        const long long gb = (long long)(n0 + lrow) * ldb + k0 + lc16 * 8;
        cp16(base + lso,              Ah + ga);
        cp16(base + TILE_B + lso,     Al + ga);
        cp16(base + 2 * TILE_B + lso, Bh + gb);
        cp16(base + 3 * TILE_B + lso, Bl + gb);
        asm volatile("cp.async.commit_group;" ::: "memory");
    };

    float acc[4][4][4];
#pragma unroll
    for (int i = 0; i < 4; ++i)
#pragma unroll
        for (int j = 0; j < 4; ++j)
#pragma unroll
            for (int q = 0; q < 4; ++q) acc[i][j][q] = 0.f;

    const int wm = (wid & 1) * 64;       // warp m offset (0/64)
    const int wn = (wid >> 1) * 32;      // warp n offset (0..96)
    const int gr = lane >> 3;
    const int rr = lane & 7;

    const uint32_t a_off = (uint32_t)((wm + (gr & 1) * 8 + rr) * SA + (gr >> 1) * 8) * 2;
    const uint32_t b_off = (uint32_t)((wn + (gr >> 1) * 8 + rr) * SA + (gr & 1) * 8) * 2;

    // prologue: prefetch 3 chunks
    if (0 < NC) load_stage(0, 0);
    if (1 < NC) load_stage(1, 1);
    if (2 < NC) load_stage(2, 2);

    for (int c = 0; c < NC; ++c) {
        // wait until group c complete (allowed pending = min(2, NC-1-c))
        const int rem = NC - 1 - c;
        if (rem >= 2)      asm volatile("cp.async.wait_group 2;" ::: "memory");
        else if (rem == 1) asm volatile("cp.async.wait_group 1;" ::: "memory");
        else               asm volatile("cp.async.wait_group 0;" ::: "memory");
        __syncthreads();   // publish stage c; all warps done with chunk c-1
        if (c + 3 < NC) load_stage((c + 3) & 3, c + 3);

        const uint32_t st = sb + (c & 3) * STAGE_B;
        // B fragments resident (hi+lo): 16 regs
        uint32_t bh[4][2], bl[4][2];
#pragma unroll
        for (int nt = 0; nt < 2; ++nt) {
            uint32_t r[4];
            ldmx4(r, st + 2 * TILE_B + b_off + (uint32_t)(nt * 16 * SA) * 2);
            bh[nt * 2 + 0][0] = r[0]; bh[nt * 2 + 0][1] = r[1];
            bh[nt * 2 + 1][0] = r[2]; bh[nt * 2 + 1][1] = r[3];
            ldmx4(r, st + 3 * TILE_B + b_off + (uint32_t)(nt * 16 * SA) * 2);
            bl[nt * 2 + 0][0] = r[0]; bl[nt * 2 + 0][1] = r[1];
            bl[nt * 2 + 1][0] = r[2]; bl[nt * 2 + 1][1] = r[3];
        }
        // A streamed per-mi; split terms interleaved across nj (dep spacing 4)
#pragma unroll
        for (int mi = 0; mi < 4; ++mi) {
            uint32_t ah[4], al[4];
            const uint32_t off = a_off + (uint32_t)(mi * 16 * SA) * 2;
            ldmx4(ah, st + off);
            ldmx4(al, st + TILE_B + off);
#pragma unroll
            for (int nj = 0; nj < 4; ++nj) mma16816(acc[mi][nj], ah, bh[nj]);
#pragma unroll
            for (int nj = 0; nj < 4; ++nj) mma16816(acc[mi][nj], al, bh[nj]);
#pragma unroll
            for (int nj = 0; nj < 4; ++nj) mma16816(acc[mi][nj], ah, bl[nj]);
        }
        // no trailing barrier: next iteration's barrier protects buffer reuse
    }

    // ---- epilogue ----
    if (mode == 0) {
#pragma unroll
        for (int mi = 0; mi < 4; ++mi)
#pragma unroll
            for (int nj = 0; nj < 4; ++nj) {
                const int row = m0 + wm + mi * 16 + (lane >> 2);
                const int col = n0 + wn + nj * 8 + (lane & 3) * 2;
                float2 v0 = make_float2(alpha * acc[mi][nj][0], alpha * acc[mi][nj][1]);
                float2 v1 = make_float2(alpha * acc[mi][nj][2], alpha * acc[mi][nj][3]);
                *(float2*)(C + (long long)row * ldc + col)       = v0;
                *(float2*)(C + (long long)(row + 8) * ldc + col) = v1;
            }
    } else {
        const int seg = n0 >> 10;                      // 0=q 1=k 2=v
        __nv_bfloat16* dh = (seg == 0) ? g_qh : g_kh;
        __nv_bfloat16* dl = (seg == 0) ? g_ql : g_kl;
#pragma unroll
        for (int mi = 0; mi < 4; ++mi)
#pragma unroll
            for (int nj = 0; nj < 4; ++nj) {
                const int row = m0 + wm + mi * 16 + (lane >> 2);
                const int cc  = (n0 & 1023) + wn + nj * 8 + (lane & 3) * 2;
                const float v00 = acc[mi][nj][0], v01 = acc[mi][nj][1];
                const float v10 = acc[mi][nj][2], v11 = acc[mi][nj][3];
                if (seg == 2) {
                    *(float2*)(g_vf + (long long)row * 1024 + cc)       = make_float2(v00, v01);
                    *(float2*)(g_vf + (long long)(row + 8) * 1024 + cc) = make_float2(v10, v11);
                } else {
                    const long long o0 = (long long)row * 1024 + cc;
                    const long long o1 = (long long)(row + 8) * 1024 + cc;
                    __nv_bfloat16 h00 = __float2bfloat16(v00), h01 = __float2bfloat16(v01);
                    __nv_bfloat16 h10 = __float2bfloat16(v10), h11 = __float2bfloat16(v11);
                    *(uint32_t*)(dh + o0) = ((uint32_t)*(uint16_t*)&h01 << 16) | *(uint16_t*)&h00;
                    *(uint32_t*)(dh + o1) = ((uint32_t)*(uint16_t*)&h11 << 16) | *(uint16_t*)&h10;
                    *(uint32_t*)(dl + o0) = pack2bf(v00 - __bfloat162float(h00),
                                                    v01 - __bfloat162float(h01));
                    *(uint32_t*)(dl + o1) = pack2bf(v10 - __bfloat162float(h10),
                                                    v11 - __bfloat162float(h11));
                }
            }
    }
}

// --------------------- merged input split (x and w) ------------------------
#define X_N4 (8192LL * 1024 / 4)
#define W_N4 (3072LL * 1024 / 4)
__global__ void split_xw_kernel(const float* __restrict__ x, const float* __restrict__ w,
                                __nv_bfloat16* __restrict__ xh, __nv_bfloat16* __restrict__ xl,
                                __nv_bfloat16* __restrict__ wh, __nv_bfloat16* __restrict__ wl)
{
    long long i = (long long)blockIdx.x * blockDim.x + threadIdx.x;
    const float* src;
    __nv_bfloat16 *h, *l;
    long long o;
    if (i < X_N4) { src = x; h = xh; l = xl; o = i; }
    else {
        o = i - X_N4;
        if (o >= W_N4) return;
        src = w; h = wh; l = wl;
    }
    float4 v = *(const float4*)(src + o * 4);
    __nv_bfloat16 hv[4], lv[4];
#pragma unroll
    for (int q = 0; q < 4; ++q) {
        float f = (&v.x)[q];
        hv[q] = __float2bfloat16(f);
        lv[q] = __float2bfloat16(f - __bfloat162float(hv[q]));
    }
    *(uint2*)(h + o * 4) = *(uint2*)hv;
    *(uint2*)(l + o * 4) = *(uint2*)lv;
}

__global__ void vtrans_kernel(const float* __restrict__ vf,
                              __nv_bfloat16* __restrict__ vth, __nv_bfloat16* __restrict__ vtl)
{
    __shared__ float tile[32][33];
    const int s0 = blockIdx.x * 32, c0 = blockIdx.y * 32, b = blockIdx.z;
    const int tx = threadIdx.x, ty = threadIdx.y;
#pragma unroll
    for (int j = 0; j < 4; ++j) {
        const int s = s0 + ty + j * 8;
        tile[ty + j * 8][tx] = vf[(long long)(b * 2048 + s) * 1024 + c0 + tx];
    }
    __syncthreads();
#pragma unroll
    for (int j = 0; j < 4; ++j) {
        const int c = c0 + ty + j * 8;
        const float v = tile[tx][ty + j * 8];
        const long long o = ((long long)b * 1024 + c) * 2048 + s0 + tx;
        __nv_bfloat16 h = __float2bfloat16(v);
        vth[o] = h;
        vtl[o] = __float2bfloat16(v - __bfloat162float(h));
    }
}

// --------------------- causal softmax -> bf16 hi/lo ------------------------
__global__ void softmax_causal_kernel(const float* __restrict__ att,
                                      __nv_bfloat16* __restrict__ ph,
                                      __nv_bfloat16* __restrict__ pl)
{
    const int row = blockIdx.x;
    const int b = row >> 11, t = row & 2047;
    const float* p = att + ((long long)b * 2048 + t) * 2048;
    __nv_bfloat16* hrow = ph + ((long long)b * 2048 + t) * 2048;
    __nv_bfloat16* lrow = pl + ((long long)b * 2048 + t) * 2048;
    const int n = t + 1;
    const int zb = ((t >> 7) + 1) << 7;
    const int tid = threadIdx.x;
    __shared__ float sbuf[8];

    float e[8];
    float m = -3.4e38f;
#pragma unroll
    for (int j = 0; j < 8; ++j) {
        const int i = tid + j * 256;
        e[j] = (i < n) ? p[i] : -3.4e38f;
        m = fmaxf(m, e[j]);
    }
#pragma unroll
    for (int o = 16; o > 0; o >>= 1) m = fmaxf(m, __shfl_xor_sync(0xffffffffu, m, o));
    if ((tid & 31) == 0) sbuf[tid >> 5] = m;
    __syncthreads();
    if (tid < 8) {
        float v = sbuf[tid];
#pragma unroll
        for (int o = 4; o > 0; o >>= 1) v = fmaxf(v, __shfl_xor_sync(0xffu, v, o));
        if (tid == 0) sbuf[0] = v;
    }
    __syncthreads();
    m = sbuf[0];
    __syncthreads();

    float s = 0.f;
#pragma unroll
    for (int j = 0; j < 8; ++j) {
        const int i = tid + j * 256;
        e[j] = (i < n) ? __expf(e[j] - m) : 0.f;
        s += e[j];
    }
#pragma unroll
    for (int o = 16; o > 0; o >>= 1) s += __shfl_xor_sync(0xffffffffu, s, o);
    if ((tid & 31) == 0) sbuf[tid >> 5] = s;
    __syncthreads();
    if (tid < 8) {
        float v = sbuf[tid];
#pragma unroll
        for (int o = 4; o > 0; o >>= 1) v += __shfl_xor_sync(0xffu, v, o);
        if (tid == 0) sbuf[0] = v;
    }
    __syncthreads();
    const float inv = 1.f / sbuf[0];

#pragma unroll
    for (int j = 0; j < 8; ++j) {
        const int i = tid + j * 256;
        if (i >= zb) break;
        const float v = e[j] * inv;
        const __nv_bfloat16 h = __float2bfloat16(v);
        hrow[i] = h;
        lrow[i] = __float2bfloat16(v - __bfloat162float(h));
    }
}

// ---------------------------------------------------------------------------
extern "C" void kernel_launch(void* const* d_in, const int* in_sizes, int n_in,
                              void* d_out, int out_size)
{
    const float* x = (const float*)d_in[0];
    const float* w = (const float*)d_in[1];
    float* out = (float*)d_out;

    float *att, *vf;
    __nv_bfloat16 *xh, *xl, *wh, *wl, *qh, *ql, *kh, *kl, *vth, *vtl, *phb, *plb;
    cudaGetSymbolAddress((void**)&att, g_att);
    cudaGetSymbolAddress((void**)&vf, g_vf);
    cudaGetSymbolAddress((void**)&xh, g_xh);   cudaGetSymbolAddress((void**)&xl, g_xl);
    cudaGetSymbolAddress((void**)&wh, g_wh);   cudaGetSymbolAddress((void**)&wl, g_wl);
    cudaGetSymbolAddress((void**)&qh, g_qh);   cudaGetSymbolAddress((void**)&ql, g_ql);
    cudaGetSymbolAddress((void**)&kh, g_kh);   cudaGetSymbolAddress((void**)&kl, g_kl);
    cudaGetSymbolAddress((void**)&vth, g_vth); cudaGetSymbolAddress((void**)&vtl, g_vtl);
    cudaGetSymbolAddress((void**)&phb, g_ph);  cudaGetSymbolAddress((void**)&plb, g_pl);

    cudaFuncSetAttribute(gemm3_kernel, cudaFuncAttributeMaxDynamicSharedMemorySize,
                         GEMM_SMEM);

    // 0) split x and w (single launch)
    {
        const long long total = X_N4 + W_N4;
        split_xw_kernel<<<(int)((total + 255) / 256), 256>>>(x, w, xh, xl, wh, wl);
    }
    // 1) qkv = x @ w^T  (fused split epilogue)
    {
        dim3 grid(3072 / 128, 8192 / 128, 1);
        gemm3_kernel<<<grid, 256, GEMM_SMEM>>>(xh, xl, wh, wl, nullptr,
                                               1024, 1024, 1024, 0,
                                               0, 0, 0, 1.0f, 0, 0, 1, 0);
    }
    // 2) transpose+split v
    {
        dim3 grid(2048 / 32, 1024 / 32, 4);
        vtrans_kernel<<<grid, dim3(32, 8)>>>(vf, vth, vtl);
    }
    // 3) S = q k^T / 32  (causal tile skip; heavy rows first)  [profiled slot]
    {
        dim3 grid(2048 / 128, 2048 / 128, 4);
        gemm3_kernel<<<grid, 256, GEMM_SMEM>>>(qh, ql, kh, kl, att,
                                               1024, 1024, 1024, 2048,
                                               2048LL * 1024, 2048LL * 1024, 2048LL * 2048,
                                               0.03125f, 1, 0, 0, 1);
    }
    // 4) P = softmax(S) -> bf16 hi/lo
    softmax_causal_kernel<<<4 * 2048, 256>>>(att, phb, plb);

    // 5) y = P @ V  (V^T K-major, causal K-limit; heavy rows first)
    {
        dim3 grid(1024 / 128, 2048 / 128, 4);
        gemm3_kernel<<<grid, 256, GEMM_SMEM>>>(phb, plb, vth, vtl, out,
                                               2048, 2048, 2048, 1024,
                                               2048LL * 2048, 1024LL * 2048, 2048LL * 1024,
                                               1.0f, 0, 1, 0, 1);
    }
}

// round 9
// speedup vs baseline: 1.1549x; 1.1549x over previous
#include <cuda_runtime.h>
#include <cuda_bf16.h>
#include <cstdint>
#include <math.h>

// ---------------------------------------------------------------------------
// SingleHeadAttention B=4, T=2048, C=1024 fp32 — bf16-split mma.sync GEMMs
//   qkv = x @ w^T   (NT, fused epilogue -> qh/ql, kh/kl, v fp32)
//   S   = q k^T/32  (NT per batch, causal tile-skip)  -> att fp32
//   P   = softmax   -> bf16 hi/lo (register-resident, 128-aligned zero bound)
//   y   = P @ (V^T)^T (NT per batch, causal K-limit)
// GEMM: C = Ah*Bh^T + Ah*Bl^T + Al*Bh^T, fp32 accum.
// R9: R7 config (CTA 128x128, 256 thr, 8 warps 2m x 4n of 64x32, kc=32,
//     2-stage, 80KB -> 2 CTAs/SM) + A-fragment double buffering +
//     single barrier per chunk (load issued after the sync).
// ---------------------------------------------------------------------------

// ------------------------------ scratch ------------------------------------
__device__ float g_att[(size_t)4 * 2048 * 2048];
__device__ float g_vf[(size_t)4 * 2048 * 1024];
__device__ __nv_bfloat16 g_xh[(size_t)8192 * 1024];
__device__ __nv_bfloat16 g_xl[(size_t)8192 * 1024];
__device__ __nv_bfloat16 g_wh[(size_t)3072 * 1024];
__device__ __nv_bfloat16 g_wl[(size_t)3072 * 1024];
__device__ __nv_bfloat16 g_qh[(size_t)4 * 2048 * 1024];
__device__ __nv_bfloat16 g_ql[(size_t)4 * 2048 * 1024];
__device__ __nv_bfloat16 g_kh[(size_t)4 * 2048 * 1024];
__device__ __nv_bfloat16 g_kl[(size_t)4 * 2048 * 1024];
__device__ __nv_bfloat16 g_vth[(size_t)4 * 1024 * 2048];
__device__ __nv_bfloat16 g_vtl[(size_t)4 * 1024 * 2048];
__device__ __nv_bfloat16 g_ph[(size_t)4 * 2048 * 2048];
__device__ __nv_bfloat16 g_pl[(size_t)4 * 2048 * 2048];

// ------------------------------ helpers ------------------------------------
#define SA 40                                 // padded smem row stride (bf16)
#define TILE_B (128 * SA * 2)                 // 10240 per operand tile (128r x 32k)
#define STAGE_B (4 * TILE_B)                  // Ah, Al, Bh, Bl = 40960
#define GEMM_SMEM (2 * STAGE_B)               // 81920 -> 2 CTAs/SM

__device__ __forceinline__ uint32_t smem_u32(const void* p) {
    uint32_t a;
    asm("{ .reg .u64 t; cvta.to.shared.u64 t, %1; cvt.u32.u64 %0, t; }" : "=r"(a) : "l"(p));
    return a;
}
__device__ __forceinline__ void cp16(uint32_t dst, const void* src) {
    asm volatile("cp.async.cg.shared.global [%0], [%1], 16;" :: "r"(dst), "l"(src));
}
__device__ __forceinline__ void ldmx4(uint32_t* r, uint32_t addr) {
    asm volatile("ldmatrix.sync.aligned.m8n8.x4.shared.b16 {%0,%1,%2,%3}, [%4];"
                 : "=r"(r[0]), "=r"(r[1]), "=r"(r[2]), "=r"(r[3]) : "r"(addr));
}
__device__ __forceinline__ void mma16816(float* c, const uint32_t* a, const uint32_t* b) {
    asm volatile(
        "mma.sync.aligned.m16n8k16.row.col.f32.bf16.bf16.f32 "
        "{%0,%1,%2,%3}, {%4,%5,%6,%7}, {%8,%9}, {%0,%1,%2,%3};"
        : "+f"(c[0]), "+f"(c[1]), "+f"(c[2]), "+f"(c[3])
        : "r"(a[0]), "r"(a[1]), "r"(a[2]), "r"(a[3]), "r"(b[0]), "r"(b[1]));
}
__device__ __forceinline__ uint32_t pack2bf(float v0, float v1) {
    __nv_bfloat16 h0 = __float2bfloat16(v0), h1 = __float2bfloat16(v1);
    return ((uint32_t)*(uint16_t*)&h1 << 16) | *(uint16_t*)&h0;
}

// ------------------------------ GEMM ---------------------------------------
// mode 0: C = alpha * acc (fp32);  mode 1: fused qkv split epilogue
__global__ __launch_bounds__(256, 2)
void gemm3_kernel(const __nv_bfloat16* __restrict__ Ah, const __nv_bfloat16* __restrict__ Al,
                  const __nv_bfloat16* __restrict__ Bh, const __nv_bfloat16* __restrict__ Bl,
                  float* __restrict__ C,
                  int K, int lda, int ldb, int ldc,
                  long long sAo, long long sBo, long long sCo,
                  float alpha, int causal_skip, int causal_klim, int mode, int rev_y)
{
    const int by = rev_y ? (gridDim.y - 1 - blockIdx.y) : blockIdx.y;
    const int m0 = by * 128;
    const int n0 = blockIdx.x * 128;
    if (causal_skip && n0 > m0 + 127) return;

    const int bz = blockIdx.z;
    Ah += (long long)bz * sAo;  Al += (long long)bz * sAo;
    Bh += (long long)bz * sBo;  Bl += (long long)bz * sBo;
    C  += (long long)bz * sCo;

    int Keff = K;
    if (causal_klim) { int lim = m0 + 128; Keff = (lim < K) ? lim : K; }
    const int NC = Keff / 32;

    extern __shared__ char smem[];
    const uint32_t sb = smem_u32(smem);
    const int tid = threadIdx.x;
    const int wid = tid >> 5;
    const int lane = tid & 31;

    // stage loader: 4 tiles of [128 rows x 32 bf16]; 128r x 4 chunks = 512 ids
    auto load_stage = [&](int s, int c) {
        const uint32_t base = sb + s * STAGE_B;
        const int k0 = c * 32;
#pragma unroll
        for (int it = 0; it < 2; ++it) {
            const int id  = tid + it * 256;
            const int row = id >> 2;
            const int c16 = id & 3;
            const uint32_t so = (uint32_t)(row * SA + c16 * 8) * 2;
            const long long ga = (long long)(m0 + row) * lda + k0 + c16 * 8;
            const long long gb = (long long)(n0 + row) * ldb + k0 + c16 * 8;
            cp16(base + so,              Ah + ga);
            cp16(base + TILE_B + so,     Al + ga);
            cp16(base + 2 * TILE_B + so, Bh + gb);
            cp16(base + 3 * TILE_B + so, Bl + gb);
        }
        asm volatile("cp.async.commit_group;" ::: "memory");
    };

    float acc[4][4][4];
#pragma unroll
    for (int i = 0; i < 4; ++i)
#pragma unroll
        for (int j = 0; j < 4; ++j)
#pragma unroll
            for (int q = 0; q < 4; ++q) acc[i][j][q] = 0.f;

    const int wm = (wid & 1) * 64;       // warp m offset (0/64)
    const int wn = (wid >> 1) * 32;      // warp n offset (0..96)
    const int gr = lane >> 3;
    const int rr = lane & 7;

    const uint32_t a_off = (uint32_t)((wm + (gr & 1) * 8 + rr) * SA + (gr >> 1) * 8) * 2;
    const uint32_t b_off = (uint32_t)((wn + (gr >> 1) * 8 + rr) * SA + (gr & 1) * 8) * 2;

    load_stage(0, 0);

    for (int c = 0; c < NC; ++c) {
        // wait for stage c (issued last iteration); then all warps are done
        // with stage c-1, so prefetching into (c+1)&1 after the sync is safe.
        asm volatile("cp.async.wait_group 0;" ::: "memory");
        __syncthreads();
        if (c + 1 < NC) load_stage((c + 1) & 1, c + 1);

        const uint32_t st = sb + (c & 1) * STAGE_B;
#pragma unroll
        for (int kk = 0; kk < 32; kk += 16) {
            const uint32_t koff = (uint32_t)kk * 2;
            // B fragments (hi+lo) for this k-half: 16 regs
            uint32_t bh[4][2], bl[4][2];
#pragma unroll
            for (int nt = 0; nt < 2; ++nt) {
                uint32_t r[4];
                ldmx4(r, st + 2 * TILE_B + b_off + koff + (uint32_t)(nt * 16 * SA) * 2);
                bh[nt * 2 + 0][0] = r[0]; bh[nt * 2 + 0][1] = r[1];
                bh[nt * 2 + 1][0] = r[2]; bh[nt * 2 + 1][1] = r[3];
                ldmx4(r, st + 3 * TILE_B + b_off + koff + (uint32_t)(nt * 16 * SA) * 2);
                bl[nt * 2 + 0][0] = r[0]; bl[nt * 2 + 0][1] = r[1];
                bl[nt * 2 + 1][0] = r[2]; bl[nt * 2 + 1][1] = r[3];
            }
            // A fragments double-buffered: prefetch mi+1 while mi computes
            uint32_t ab[2][2][4];                 // [parity][h/l][4]
            ldmx4(ab[0][0], st + a_off + koff);
            ldmx4(ab[0][1], st + TILE_B + a_off + koff);
#pragma unroll
            for (int mi = 0; mi < 4; ++mi) {
                const int cur = mi & 1, nxt = cur ^ 1;
                if (mi < 3) {
                    const uint32_t off = a_off + koff + (uint32_t)((mi + 1) * 16 * SA) * 2;
                    ldmx4(ab[nxt][0], st + off);
                    ldmx4(ab[nxt][1], st + TILE_B + off);
                }
#pragma unroll
                for (int nj = 0; nj < 4; ++nj) mma16816(acc[mi][nj], ab[cur][0], bh[nj]);
#pragma unroll
                for (int nj = 0; nj < 4; ++nj) mma16816(acc[mi][nj], ab[cur][1], bh[nj]);
#pragma unroll
                for (int nj = 0; nj < 4; ++nj) mma16816(acc[mi][nj], ab[cur][0], bl[nj]);
            }
        }
        // single barrier per chunk: next iteration's sync protects reuse
    }

    // ---- epilogue ----
    if (mode == 0) {
#pragma unroll
        for (int mi = 0; mi < 4; ++mi)
#pragma unroll
            for (int nj = 0; nj < 4; ++nj) {
                const int row = m0 + wm + mi * 16 + (lane >> 2);
                const int col = n0 + wn + nj * 8 + (lane & 3) * 2;
                float2 v0 = make_float2(alpha * acc[mi][nj][0], alpha * acc[mi][nj][1]);
                float2 v1 = make_float2(alpha * acc[mi][nj][2], alpha * acc[mi][nj][3]);
                *(float2*)(C + (long long)row * ldc + col)       = v0;
                *(float2*)(C + (long long)(row + 8) * ldc + col) = v1;
            }
    } else {
        const int seg = n0 >> 10;                      // 0=q 1=k 2=v
        __nv_bfloat16* dh = (seg == 0) ? g_qh : g_kh;
        __nv_bfloat16* dl = (seg == 0) ? g_ql : g_kl;
#pragma unroll
        for (int mi = 0; mi < 4; ++mi)
#pragma unroll
            for (int nj = 0; nj < 4; ++nj) {
                const int row = m0 + wm + mi * 16 + (lane >> 2);
                const int cc  = (n0 & 1023) + wn + nj * 8 + (lane & 3) * 2;
                const float v00 = acc[mi][nj][0], v01 = acc[mi][nj][1];
                const float v10 = acc[mi][nj][2], v11 = acc[mi][nj][3];
                if (seg == 2) {
                    *(float2*)(g_vf + (long long)row * 1024 + cc)       = make_float2(v00, v01);
                    *(float2*)(g_vf + (long long)(row + 8) * 1024 + cc) = make_float2(v10, v11);
                } else {
                    const long long o0 = (long long)row * 1024 + cc;
                    const long long o1 = (long long)(row + 8) * 1024 + cc;
                    __nv_bfloat16 h00 = __float2bfloat16(v00), h01 = __float2bfloat16(v01);
                    __nv_bfloat16 h10 = __float2bfloat16(v10), h11 = __float2bfloat16(v11);
                    *(uint32_t*)(dh + o0) = ((uint32_t)*(uint16_t*)&h01 << 16) | *(uint16_t*)&h00;
                    *(uint32_t*)(dh + o1) = ((uint32_t)*(uint16_t*)&h11 << 16) | *(uint16_t*)&h10;
                    *(uint32_t*)(dl + o0) = pack2bf(v00 - __bfloat162float(h00),
                                                    v01 - __bfloat162float(h01));
                    *(uint32_t*)(dl + o1) = pack2bf(v10 - __bfloat162float(h10),
                                                    v11 - __bfloat162float(h11));
                }
            }
    }
}

// --------------------- merged input split (x and w) ------------------------
#define X_N4 (8192LL * 1024 / 4)
#define W_N4 (3072LL * 1024 / 4)
__global__ void split_xw_kernel(const float* __restrict__ x, const float* __restrict__ w,
                                __nv_bfloat16* __restrict__ xh, __nv_bfloat16* __restrict__ xl,
                                __nv_bfloat16* __restrict__ wh, __nv_bfloat16* __restrict__ wl)
{
    long long i = (long long)blockIdx.x * blockDim.x + threadIdx.x;
    const float* src;
    __nv_bfloat16 *h, *l;
    long long o;
    if (i < X_N4) { src = x; h = xh; l = xl; o = i; }
    else {
        o = i - X_N4;
        if (o >= W_N4) return;
        src = w; h = wh; l = wl;
    }
    float4 v = *(const float4*)(src + o * 4);
    __nv_bfloat16 hv[4], lv[4];
#pragma unroll
    for (int q = 0; q < 4; ++q) {
        float f = (&v.x)[q];
        hv[q] = __float2bfloat16(f);
        lv[q] = __float2bfloat16(f - __bfloat162float(hv[q]));
    }
    *(uint2*)(h + o * 4) = *(uint2*)hv;
    *(uint2*)(l + o * 4) = *(uint2*)lv;
}

__global__ void vtrans_kernel(const float* __restrict__ vf,
                              __nv_bfloat16* __restrict__ vth, __nv_bfloat16* __restrict__ vtl)
{
    __shared__ float tile[32][33];
    const int s0 = blockIdx.x * 32, c0 = blockIdx.y * 32, b = blockIdx.z;
    const int tx = threadIdx.x, ty = threadIdx.y;
#pragma unroll
    for (int j = 0; j < 4; ++j) {
        const int s = s0 + ty + j * 8;
        tile[ty + j * 8][tx] = vf[(long long)(b * 2048 + s) * 1024 + c0 + tx];
    }
    __syncthreads();
#pragma unroll
    for (int j = 0; j < 4; ++j) {
        const int c = c0 + ty + j * 8;
        const float v = tile[tx][ty + j * 8];
        const long long o = ((long long)b * 1024 + c) * 2048 + s0 + tx;
        __nv_bfloat16 h = __float2bfloat16(v);
        vth[o] = h;
        vtl[o] = __float2bfloat16(v - __bfloat162float(h));
    }
}

// --------------------- causal softmax -> bf16 hi/lo ------------------------
__global__ void softmax_causal_kernel(const float* __restrict__ att,
                                      __nv_bfloat16* __restrict__ ph,
                                      __nv_bfloat16* __restrict__ pl)
{
    const int row = blockIdx.x;
    const int b = row >> 11, t = row & 2047;
    const float* p = att + ((long long)b * 2048 + t) * 2048;
    __nv_bfloat16* hrow = ph + ((long long)b * 2048 + t) * 2048;
    __nv_bfloat16* lrow = pl + ((long long)b * 2048 + t) * 2048;
    const int n = t + 1;
    const int zb = ((t >> 7) + 1) << 7;
    const int tid = threadIdx.x;
    __shared__ float sbuf[8];

    float e[8];
    float m = -3.4e38f;
#pragma unroll
    for (int j = 0; j < 8; ++j) {
        const int i = tid + j * 256;
        e[j] = (i < n) ? p[i] : -3.4e38f;
        m = fmaxf(m, e[j]);
    }
#pragma unroll
    for (int o = 16; o > 0; o >>= 1) m = fmaxf(m, __shfl_xor_sync(0xffffffffu, m, o));
    if ((tid & 31) == 0) sbuf[tid >> 5] = m;
    __syncthreads();
    if (tid < 8) {
        float v = sbuf[tid];
#pragma unroll
        for (int o = 4; o > 0; o >>= 1) v = fmaxf(v, __shfl_xor_sync(0xffu, v, o));
        if (tid == 0) sbuf[0] = v;
    }
    __syncthreads();
    m = sbuf[0];
    __syncthreads();

    float s = 0.f;
#pragma unroll
    for (int j = 0; j < 8; ++j) {
        const int i = tid + j * 256;
        e[j] = (i < n) ? __expf(e[j] - m) : 0.f;
        s += e[j];
    }
#pragma unroll
    for (int o = 16; o > 0; o >>= 1) s += __shfl_xor_sync(0xffffffffu, s, o);
    if ((tid & 31) == 0) sbuf[tid >> 5] = s;
    __syncthreads();
    if (tid < 8) {
        float v = sbuf[tid];
#pragma unroll
        for (int o = 4; o > 0; o >>= 1) v += __shfl_xor_sync(0xffu, v, o);
        if (tid == 0) sbuf[0] = v;
    }
    __syncthreads();
    const float inv = 1.f / sbuf[0];

#pragma unroll
    for (int j = 0; j < 8; ++j) {
        const int i = tid + j * 256;
        if (i >= zb) break;
        const float v = e[j] * inv;
        const __nv_bfloat16 h = __float2bfloat16(v);
        hrow[i] = h;
        lrow[i] = __float2bfloat16(v - __bfloat162float(h));
    }
}

// ---------------------------------------------------------------------------
extern "C" void kernel_launch(void* const* d_in, const int* in_sizes, int n_in,
                              void* d_out, int out_size)
{
    const float* x = (const float*)d_in[0];
    const float* w = (const float*)d_in[1];
    float* out = (float*)d_out;

    float *att, *vf;
    __nv_bfloat16 *xh, *xl, *wh, *wl, *qh, *ql, *kh, *kl, *vth, *vtl, *phb, *plb;
    cudaGetSymbolAddress((void**)&att, g_att);
    cudaGetSymbolAddress((void**)&vf, g_vf);
    cudaGetSymbolAddress((void**)&xh, g_xh);   cudaGetSymbolAddress((void**)&xl, g_xl);
    cudaGetSymbolAddress((void**)&wh, g_wh);   cudaGetSymbolAddress((void**)&wl, g_wl);
    cudaGetSymbolAddress((void**)&qh, g_qh);   cudaGetSymbolAddress((void**)&ql, g_ql);
    cudaGetSymbolAddress((void**)&kh, g_kh);   cudaGetSymbolAddress((void**)&kl, g_kl);
    cudaGetSymbolAddress((void**)&vth, g_vth); cudaGetSymbolAddress((void**)&vtl, g_vtl);
    cudaGetSymbolAddress((void**)&phb, g_ph);  cudaGetSymbolAddress((void**)&plb, g_pl);

    cudaFuncSetAttribute(gemm3_kernel, cudaFuncAttributeMaxDynamicSharedMemorySize,
                         GEMM_SMEM);

    // 0) split x and w (single launch)
    {
        const long long total = X_N4 + W_N4;
        split_xw_kernel<<<(int)((total + 255) / 256), 256>>>(x, w, xh, xl, wh, wl);
    }
    // 1) qkv = x @ w^T  (fused split epilogue)
    {
        dim3 grid(3072 / 128, 8192 / 128, 1);
        gemm3_kernel<<<grid, 256, GEMM_SMEM>>>(xh, xl, wh, wl, nullptr,
                                               1024, 1024, 1024, 0,
                                               0, 0, 0, 1.0f, 0, 0, 1, 0);
    }
    // 2) transpose+split v
    {
        dim3 grid(2048 / 32, 1024 / 32, 4);
        vtrans_kernel<<<grid, dim3(32, 8)>>>(vf, vth, vtl);
    }
    // 3) S = q k^T / 32  (causal tile skip; heavy rows first)  [profiled slot]
    {
        dim3 grid(2048 / 128, 2048 / 128, 4);
        gemm3_kernel<<<grid, 256, GEMM_SMEM>>>(qh, ql, kh, kl, att,
                                               1024, 1024, 1024, 2048,
                                               2048LL * 1024, 2048LL * 1024, 2048LL * 2048,
                                               0.03125f, 1, 0, 0, 1);
    }
    // 4) P = softmax(S) -> bf16 hi/lo
    softmax_causal_kernel<<<4 * 2048, 256>>>(att, phb, plb);

    // 5) y = P @ V  (V^T K-major, causal K-limit; heavy rows first)
    {
        dim3 grid(1024 / 128, 2048 / 128, 4);
        gemm3_kernel<<<grid, 256, GEMM_SMEM>>>(phb, plb, vth, vtl, out,
                                               2048, 2048, 2048, 1024,
                                               2048LL * 2048, 1024LL * 2048, 2048LL * 1024,
                                               1.0f, 0, 1, 0, 1);
    }
}

// round 10
// speedup vs baseline: 1.1824x; 1.0238x over previous
#include <cuda_runtime.h>
#include <cuda_bf16.h>
#include <cstdint>
#include <math.h>

// ---------------------------------------------------------------------------
// SingleHeadAttention B=4, T=2048, C=1024 fp32 — bf16-split mma.sync GEMMs
//   qkv = x @ w^T   (NT, fused epilogue -> qh/ql, kh/kl, v fp32)
//   S   = q k^T/32  (NT per batch, causal tile-skip)  -> att fp32
//   P   = softmax   -> bf16 hi/lo (register-resident, 128-aligned zero bound)
//   y   = P @ (V^T)^T (NT per batch, causal K-limit)
// GEMM: C = Ah*Bh^T + Ah*Bl^T + Al*Bh^T, fp32 accum.
// R10: CTA 128x128, 256 thr, 8 warps (2m x 4n of 64x32), kc=32, 3-stage,
//      1 CTA/SM with NO 128-reg cap: full A+B fragment double buffering
//      across kk-halves and chunk boundaries (LDSM fully hidden by MMAs).
// ---------------------------------------------------------------------------

// ------------------------------ scratch ------------------------------------
__device__ float g_att[(size_t)4 * 2048 * 2048];
__device__ float g_vf[(size_t)4 * 2048 * 1024];
__device__ __nv_bfloat16 g_xh[(size_t)8192 * 1024];
__device__ __nv_bfloat16 g_xl[(size_t)8192 * 1024];
__device__ __nv_bfloat16 g_wh[(size_t)3072 * 1024];
__device__ __nv_bfloat16 g_wl[(size_t)3072 * 1024];
__device__ __nv_bfloat16 g_qh[(size_t)4 * 2048 * 1024];
__device__ __nv_bfloat16 g_ql[(size_t)4 * 2048 * 1024];
__device__ __nv_bfloat16 g_kh[(size_t)4 * 2048 * 1024];
__device__ __nv_bfloat16 g_kl[(size_t)4 * 2048 * 1024];
__device__ __nv_bfloat16 g_vth[(size_t)4 * 1024 * 2048];
__device__ __nv_bfloat16 g_vtl[(size_t)4 * 1024 * 2048];
__device__ __nv_bfloat16 g_ph[(size_t)4 * 2048 * 2048];
__device__ __nv_bfloat16 g_pl[(size_t)4 * 2048 * 2048];

// ------------------------------ helpers ------------------------------------
#define SA 40                                 // padded smem row stride (bf16)
#define TILE_B (128 * SA * 2)                 // 10240 per operand tile (128r x 32k)
#define STAGE_B (4 * TILE_B)                  // Ah, Al, Bh, Bl = 40960
#define NSTG 3
#define GEMM_SMEM (NSTG * STAGE_B)            // 122880 -> 1 CTA/SM
#define KOFF16 32                             // byte offset of kk=16 half

__device__ __forceinline__ uint32_t smem_u32(const void* p) {
    uint32_t a;
    asm("{ .reg .u64 t; cvta.to.shared.u64 t, %1; cvt.u32.u64 %0, t; }" : "=r"(a) : "l"(p));
    return a;
}
__device__ __forceinline__ void cp16(uint32_t dst, const void* src) {
    asm volatile("cp.async.cg.shared.global [%0], [%1], 16;" :: "r"(dst), "l"(src));
}
__device__ __forceinline__ void ldmx4(uint32_t* r, uint32_t addr) {
    asm volatile("ldmatrix.sync.aligned.m8n8.x4.shared.b16 {%0,%1,%2,%3}, [%4];"
                 : "=r"(r[0]), "=r"(r[1]), "=r"(r[2]), "=r"(r[3]) : "r"(addr));
}
__device__ __forceinline__ void mma16816(float* c, const uint32_t* a, const uint32_t* b) {
    asm volatile(
        "mma.sync.aligned.m16n8k16.row.col.f32.bf16.bf16.f32 "
        "{%0,%1,%2,%3}, {%4,%5,%6,%7}, {%8,%9}, {%0,%1,%2,%3};"
        : "+f"(c[0]), "+f"(c[1]), "+f"(c[2]), "+f"(c[3])
        : "r"(a[0]), "r"(a[1]), "r"(a[2]), "r"(a[3]), "r"(b[0]), "r"(b[1]));
}
__device__ __forceinline__ uint32_t pack2bf(float v0, float v1) {
    __nv_bfloat16 h0 = __float2bfloat16(v0), h1 = __float2bfloat16(v1);
    return ((uint32_t)*(uint16_t*)&h1 << 16) | *(uint16_t*)&h0;
}

// ------------------------------ GEMM ---------------------------------------
// mode 0: C = alpha * acc (fp32);  mode 1: fused qkv split epilogue
// Requires NC >= 3 (smallest caller NC = 4).
__global__ __launch_bounds__(256, 1)
void gemm3_kernel(const __nv_bfloat16* __restrict__ Ah, const __nv_bfloat16* __restrict__ Al,
                  const __nv_bfloat16* __restrict__ Bh, const __nv_bfloat16* __restrict__ Bl,
                  float* __restrict__ C,
                  int K, int lda, int ldb, int ldc,
                  long long sAo, long long sBo, long long sCo,
                  float alpha, int causal_skip, int causal_klim, int mode, int rev_y)
{
    const int by = rev_y ? (gridDim.y - 1 - blockIdx.y) : blockIdx.y;
    const int m0 = by * 128;
    const int n0 = blockIdx.x * 128;
    if (causal_skip && n0 > m0 + 127) return;

    const int bz = blockIdx.z;
    Ah += (long long)bz * sAo;  Al += (long long)bz * sAo;
    Bh += (long long)bz * sBo;  Bl += (long long)bz * sBo;
    C  += (long long)bz * sCo;

    int Keff = K;
    if (causal_klim) { int lim = m0 + 128; Keff = (lim < K) ? lim : K; }
    const int NC = Keff / 32;

    extern __shared__ char smem[];
    const uint32_t sb = smem_u32(smem);
    const int tid = threadIdx.x;
    const int wid = tid >> 5;
    const int lane = tid & 31;

    // stage loader: 4 tiles of [128 rows x 32 bf16]; 128r x 4 chunks = 512 ids
    auto load_stage = [&](int s, int c) {
        const uint32_t base = sb + s * STAGE_B;
        const int k0 = c * 32;
#pragma unroll
        for (int it = 0; it < 2; ++it) {
            const int id  = tid + it * 256;
            const int row = id >> 2;
            const int c16 = id & 3;
            const uint32_t so = (uint32_t)(row * SA + c16 * 8) * 2;
            const long long ga = (long long)(m0 + row) * lda + k0 + c16 * 8;
            const long long gb = (long long)(n0 + row) * ldb + k0 + c16 * 8;
            cp16(base + so,              Ah + ga);
            cp16(base + TILE_B + so,     Al + ga);
            cp16(base + 2 * TILE_B + so, Bh + gb);
            cp16(base + 3 * TILE_B + so, Bl + gb);
        }
        asm volatile("cp.async.commit_group;" ::: "memory");
    };

    float acc[4][4][4];
#pragma unroll
    for (int i = 0; i < 4; ++i)
#pragma unroll
        for (int j = 0; j < 4; ++j)
#pragma unroll
            for (int q = 0; q < 4; ++q) acc[i][j][q] = 0.f;

    const int wm = (wid & 1) * 64;       // warp m offset (0/64)
    const int wn = (wid >> 1) * 32;      // warp n offset (0..96)
    const int gr = lane >> 3;
    const int rr = lane & 7;

    const uint32_t a_off = (uint32_t)((wm + (gr & 1) * 8 + rr) * SA + (gr >> 1) * 8) * 2;
    const uint32_t b_off = (uint32_t)((wn + (gr >> 1) * 8 + rr) * SA + (gr & 1) * 8) * 2;

    // two fragment buffer sets (compile-time selected; never local memory)
    uint32_t fah0[4][4], fal0[4][4], fbh0[4][2], fbl0[4][2];
    uint32_t fah1[4][4], fal1[4][4], fbh1[4][2], fbl1[4][2];

    auto load_frags = [&](uint32_t st, uint32_t koff,
                          uint32_t (&fah)[4][4], uint32_t (&fal)[4][4],
                          uint32_t (&fbh)[4][2], uint32_t (&fbl)[4][2]) {
#pragma unroll
        for (int nt = 0; nt < 2; ++nt) {
            uint32_t r[4];
            ldmx4(r, st + 2 * TILE_B + b_off + koff + (uint32_t)(nt * 16 * SA) * 2);
            fbh[nt * 2 + 0][0] = r[0]; fbh[nt * 2 + 0][1] = r[1];
            fbh[nt * 2 + 1][0] = r[2]; fbh[nt * 2 + 1][1] = r[3];
            ldmx4(r, st + 3 * TILE_B + b_off + koff + (uint32_t)(nt * 16 * SA) * 2);
            fbl[nt * 2 + 0][0] = r[0]; fbl[nt * 2 + 0][1] = r[1];
            fbl[nt * 2 + 1][0] = r[2]; fbl[nt * 2 + 1][1] = r[3];
        }
#pragma unroll
        for (int mi = 0; mi < 4; ++mi) {
            const uint32_t off = a_off + koff + (uint32_t)(mi * 16 * SA) * 2;
            ldmx4(fah[mi], st + off);
            ldmx4(fal[mi], st + TILE_B + off);
        }
    };
    auto mma_all = [&](uint32_t (&fah)[4][4], uint32_t (&fal)[4][4],
                       uint32_t (&fbh)[4][2], uint32_t (&fbl)[4][2]) {
#pragma unroll
        for (int mi = 0; mi < 4; ++mi) {
#pragma unroll
            for (int nj = 0; nj < 4; ++nj) mma16816(acc[mi][nj], fah[mi], fbh[nj]);
#pragma unroll
            for (int nj = 0; nj < 4; ++nj) mma16816(acc[mi][nj], fal[mi], fbh[nj]);
#pragma unroll
            for (int nj = 0; nj < 4; ++nj) mma16816(acc[mi][nj], fah[mi], fbl[nj]);
        }
    };

    // prologue: 3 stages in flight; frags for (chunk0, kk=0)
    load_stage(0, 0);
    load_stage(1, 1);
    load_stage(2, 2);
    asm volatile("cp.async.wait_group 2;" ::: "memory");
    __syncthreads();
    load_frags(sb, 0, fah0, fal0, fbh0, fbl0);

    for (int c = 0; c < NC; ++c) {
        const uint32_t st = sb + (c % 3) * STAGE_B;

        // half 0: compute (c, kk=0) from set0; prefetch (c, kk=16) into set1
        load_frags(st, KOFF16, fah1, fal1, fbh1, fbl1);
        mma_all(fah0, fal0, fbh0, fbl0);

        // stage c fully read by this warp; make stage c+1 visible everywhere
        if (c + 2 < NC) asm volatile("cp.async.wait_group 1;" ::: "memory");
        else            asm volatile("cp.async.wait_group 0;" ::: "memory");
        __syncthreads();                       // joint: reads of c done + c+1 visible
        if (c + 3 < NC) load_stage(c % 3, c + 3);
        if (c + 1 < NC)
            load_frags(sb + ((c + 1) % 3) * STAGE_B, 0, fah0, fal0, fbh0, fbl0);

        // half 1: compute (c, kk=16) from set1
        mma_all(fah1, fal1, fbh1, fbl1);
    }

    // ---- epilogue ----
    if (mode == 0) {
#pragma unroll
        for (int mi = 0; mi < 4; ++mi)
#pragma unroll
            for (int nj = 0; nj < 4; ++nj) {
                const int row = m0 + wm + mi * 16 + (lane >> 2);
                const int col = n0 + wn + nj * 8 + (lane & 3) * 2;
                float2 v0 = make_float2(alpha * acc[mi][nj][0], alpha * acc[mi][nj][1]);
                float2 v1 = make_float2(alpha * acc[mi][nj][2], alpha * acc[mi][nj][3]);
                *(float2*)(C + (long long)row * ldc + col)       = v0;
                *(float2*)(C + (long long)(row + 8) * ldc + col) = v1;
            }
    } else {
        const int seg = n0 >> 10;                      // 0=q 1=k 2=v
        __nv_bfloat16* dh = (seg == 0) ? g_qh : g_kh;
        __nv_bfloat16* dl = (seg == 0) ? g_ql : g_kl;
#pragma unroll
        for (int mi = 0; mi < 4; ++mi)
#pragma unroll
            for (int nj = 0; nj < 4; ++nj) {
                const int row = m0 + wm + mi * 16 + (lane >> 2);
                const int cc  = (n0 & 1023) + wn + nj * 8 + (lane & 3) * 2;
                const float v00 = acc[mi][nj][0], v01 = acc[mi][nj][1];
                const float v10 = acc[mi][nj][2], v11 = acc[mi][nj][3];
                if (seg == 2) {
                    *(float2*)(g_vf + (long long)row * 1024 + cc)       = make_float2(v00, v01);
                    *(float2*)(g_vf + (long long)(row + 8) * 1024 + cc) = make_float2(v10, v11);
                } else {
                    const long long o0 = (long long)row * 1024 + cc;
                    const long long o1 = (long long)(row + 8) * 1024 + cc;
                    __nv_bfloat16 h00 = __float2bfloat16(v00), h01 = __float2bfloat16(v01);
                    __nv_bfloat16 h10 = __float2bfloat16(v10), h11 = __float2bfloat16(v11);
                    *(uint32_t*)(dh + o0) = ((uint32_t)*(uint16_t*)&h01 << 16) | *(uint16_t*)&h00;
                    *(uint32_t*)(dh + o1) = ((uint32_t)*(uint16_t*)&h11 << 16) | *(uint16_t*)&h10;
                    *(uint32_t*)(dl + o0) = pack2bf(v00 - __bfloat162float(h00),
                                                    v01 - __bfloat162float(h01));
                    *(uint32_t*)(dl + o1) = pack2bf(v10 - __bfloat162float(h10),
                                                    v11 - __bfloat162float(h11));
                }
            }
    }
}

// --------------------- merged input split (x and w) ------------------------
#define X_N4 (8192LL * 1024 / 4)
#define W_N4 (3072LL * 1024 / 4)
__global__ void split_xw_kernel(const float* __restrict__ x, const float* __restrict__ w,
                                __nv_bfloat16* __restrict__ xh, __nv_bfloat16* __restrict__ xl,
                                __nv_bfloat16* __restrict__ wh, __nv_bfloat16* __restrict__ wl)
{
    long long i = (long long)blockIdx.x * blockDim.x + threadIdx.x;
    const float* src;
    __nv_bfloat16 *h, *l;
    long long o;
    if (i < X_N4) { src = x; h = xh; l = xl; o = i; }
    else {
        o = i - X_N4;
        if (o >= W_N4) return;
        src = w; h = wh; l = wl;
    }
    float4 v = *(const float4*)(src + o * 4);
    __nv_bfloat16 hv[4], lv[4];
#pragma unroll
    for (int q = 0; q < 4; ++q) {
        float f = (&v.x)[q];
        hv[q] = __float2bfloat16(f);
        lv[q] = __float2bfloat16(f - __bfloat162float(hv[q]));
    }
    *(uint2*)(h + o * 4) = *(uint2*)hv;
    *(uint2*)(l + o * 4) = *(uint2*)lv;
}

__global__ void vtrans_kernel(const float* __restrict__ vf,
                              __nv_bfloat16* __restrict__ vth, __nv_bfloat16* __restrict__ vtl)
{
    __shared__ float tile[32][33];
    const int s0 = blockIdx.x * 32, c0 = blockIdx.y * 32, b = blockIdx.z;
    const int tx = threadIdx.x, ty = threadIdx.y;
#pragma unroll
    for (int j = 0; j < 4; ++j) {
        const int s = s0 + ty + j * 8;
        tile[ty + j * 8][tx] = vf[(long long)(b * 2048 + s) * 1024 + c0 + tx];
    }
    __syncthreads();
#pragma unroll
    for (int j = 0; j < 4; ++j) {
        const int c = c0 + ty + j * 8;
        const float v = tile[tx][ty + j * 8];
        const long long o = ((long long)b * 1024 + c) * 2048 + s0 + tx;
        __nv_bfloat16 h = __float2bfloat16(v);
        vth[o] = h;
        vtl[o] = __float2bfloat16(v - __bfloat162float(h));
    }
}

// --------------------- causal softmax -> bf16 hi/lo ------------------------
__global__ void softmax_causal_kernel(const float* __restrict__ att,
                                      __nv_bfloat16* __restrict__ ph,
                                      __nv_bfloat16* __restrict__ pl)
{
    const int row = blockIdx.x;
    const int b = row >> 11, t = row & 2047;
    const float* p = att + ((long long)b * 2048 + t) * 2048;
    __nv_bfloat16* hrow = ph + ((long long)b * 2048 + t) * 2048;
    __nv_bfloat16* lrow = pl + ((long long)b * 2048 + t) * 2048;
    const int n = t + 1;
    const int zb = ((t >> 7) + 1) << 7;
    const int tid = threadIdx.x;
    __shared__ float sbuf[8];

    float e[8];
    float m = -3.4e38f;
#pragma unroll
    for (int j = 0; j < 8; ++j) {
        const int i = tid + j * 256;
        e[j] = (i < n) ? p[i] : -3.4e38f;
        m = fmaxf(m, e[j]);
    }
#pragma unroll
    for (int o = 16; o > 0; o >>= 1) m = fmaxf(m, __shfl_xor_sync(0xffffffffu, m, o));
    if ((tid & 31) == 0) sbuf[tid >> 5] = m;
    __syncthreads();
    if (tid < 8) {
        float v = sbuf[tid];
#pragma unroll
        for (int o = 4; o > 0; o >>= 1) v = fmaxf(v, __shfl_xor_sync(0xffu, v, o));
        if (tid == 0) sbuf[0] = v;
    }
    __syncthreads();
    m = sbuf[0];
    __syncthreads();

    float s = 0.f;
#pragma unroll
    for (int j = 0; j < 8; ++j) {
        const int i = tid + j * 256;
        e[j] = (i < n) ? __expf(e[j] - m) : 0.f;
        s += e[j];
    }
#pragma unroll
    for (int o = 16; o > 0; o >>= 1) s += __shfl_xor_sync(0xffffffffu, s, o);
    if ((tid & 31) == 0) sbuf[tid >> 5] = s;
    __syncthreads();
    if (tid < 8) {
        float v = sbuf[tid];
#pragma unroll
        for (int o = 4; o > 0; o >>= 1) v += __shfl_xor_sync(0xffu, v, o);
        if (tid == 0) sbuf[0] = v;
    }
    __syncthreads();
    const float inv = 1.f / sbuf[0];

#pragma unroll
    for (int j = 0; j < 8; ++j) {
        const int i = tid + j * 256;
        if (i >= zb) break;
        const float v = e[j] * inv;
        const __nv_bfloat16 h = __float2bfloat16(v);
        hrow[i] = h;
        lrow[i] = __float2bfloat16(v - __bfloat162float(h));
    }
}

// ---------------------------------------------------------------------------
extern "C" void kernel_launch(void* const* d_in, const int* in_sizes, int n_in,
                              void* d_out, int out_size)
{
    const float* x = (const float*)d_in[0];
    const float* w = (const float*)d_in[1];
    float* out = (float*)d_out;

    float *att, *vf;
    __nv_bfloat16 *xh, *xl, *wh, *wl, *qh, *ql, *kh, *kl, *vth, *vtl, *phb, *plb;
    cudaGetSymbolAddress((void**)&att, g_att);
    cudaGetSymbolAddress((void**)&vf, g_vf);
    cudaGetSymbolAddress((void**)&xh, g_xh);   cudaGetSymbolAddress((void**)&xl, g_xl);
    cudaGetSymbolAddress((void**)&wh, g_wh);   cudaGetSymbolAddress((void**)&wl, g_wl);
    cudaGetSymbolAddress((void**)&qh, g_qh);   cudaGetSymbolAddress((void**)&ql, g_ql);
    cudaGetSymbolAddress((void**)&kh, g_kh);   cudaGetSymbolAddress((void**)&kl, g_kl);
    cudaGetSymbolAddress((void**)&vth, g_vth); cudaGetSymbolAddress((void**)&vtl, g_vtl);
    cudaGetSymbolAddress((void**)&phb, g_ph);  cudaGetSymbolAddress((void**)&plb, g_pl);

    cudaFuncSetAttribute(gemm3_kernel, cudaFuncAttributeMaxDynamicSharedMemorySize,
                         GEMM_SMEM);

    // 0) split x and w (single launch)
    {
        const long long total = X_N4 + W_N4;
        split_xw_kernel<<<(int)((total + 255) / 256), 256>>>(x, w, xh, xl, wh, wl);
    }
    // 1) qkv = x @ w^T  (fused split epilogue)
    {
        dim3 grid(3072 / 128, 8192 / 128, 1);
        gemm3_kernel<<<grid, 256, GEMM_SMEM>>>(xh, xl, wh, wl, nullptr,
                                               1024, 1024, 1024, 0,
                                               0, 0, 0, 1.0f, 0, 0, 1, 0);
    }
    // 2) transpose+split v
    {
        dim3 grid(2048 / 32, 1024 / 32, 4);
        vtrans_kernel<<<grid, dim3(32, 8)>>>(vf, vth, vtl);
    }
    // 3) S = q k^T / 32  (causal tile skip; heavy rows first)  [profiled slot]
    {
        dim3 grid(2048 / 128, 2048 / 128, 4);
        gemm3_kernel<<<grid, 256, GEMM_SMEM>>>(qh, ql, kh, kl, att,
                                               1024, 1024, 1024, 2048,
                                               2048LL * 1024, 2048LL * 1024, 2048LL * 2048,
                                               0.03125f, 1, 0, 0, 1);
    }
    // 4) P = softmax(S) -> bf16 hi/lo
    softmax_causal_kernel<<<4 * 2048, 256>>>(att, phb, plb);

    // 5) y = P @ V  (V^T K-major, causal K-limit; heavy rows first)
    {
        dim3 grid(1024 / 128, 2048 / 128, 4);
        gemm3_kernel<<<grid, 256, GEMM_SMEM>>>(phb, plb, vth, vtl, out,
                                               2048, 2048, 2048, 1024,
                                               2048LL * 2048, 1024LL * 2048, 2048LL * 1024,
                                               1.0f, 0, 1, 0, 1);
    }
}

// round 11
// speedup vs baseline: 1.5654x; 1.3239x over previous
#include <cuda_runtime.h>
#include <cuda_fp16.h>
#include <cstdint>
#include <math.h>

// ---------------------------------------------------------------------------
// SingleHeadAttention B=4, T=2048, C=1024 fp32 — fp16 2-term mma.sync GEMMs
//   qkv = x @ w^T   (NT, fused epilogue -> qh/ql fp16, kh fp16, v fp32)
//   S   = q k^T/32  (NT per batch, causal tile-skip)  -> att fp32
//   P   = softmax   -> fp16 hi/lo
//   y   = P @ (V^T)^T (NT per batch, causal K-limit)
// GEMM: C = Ah*Bh^T + Al*Bh^T  (A split hi/lo fp16, B single fp16, fp32 accum)
// R11: R10 skeleton (CTA 128x128, 256 thr, 8 warps 2m x 4n, kc=32, 3-stage,
//      1 CTA/SM, full A+B fragment double buffering). 3 tiles/stage.
// ---------------------------------------------------------------------------

// ------------------------------ scratch ------------------------------------
__device__ float g_att[(size_t)4 * 2048 * 2048];
__device__ float g_vf[(size_t)4 * 2048 * 1024];
__device__ __half g_xh[(size_t)8192 * 1024];
__device__ __half g_xl[(size_t)8192 * 1024];
__device__ __half g_wh[(size_t)3072 * 1024];
__device__ __half g_qh[(size_t)4 * 2048 * 1024];
__device__ __half g_ql[(size_t)4 * 2048 * 1024];
__device__ __half g_kh[(size_t)4 * 2048 * 1024];
__device__ __half g_vth[(size_t)4 * 1024 * 2048];     // V^T
__device__ __half g_ph[(size_t)4 * 2048 * 2048];
__device__ __half g_pl[(size_t)4 * 2048 * 2048];

// ------------------------------ helpers ------------------------------------
#define SA 40                                 // padded smem row stride (halfs)
#define TILE_B (128 * SA * 2)                 // 10240 per operand tile (128r x 32k)
#define STAGE_B (3 * TILE_B)                  // Ah, Al, Bh = 30720
#define NSTG 3
#define GEMM_SMEM (NSTG * STAGE_B)            // 92160 -> 1 CTA/SM (no reg cap)
#define KOFF16 32                             // byte offset of kk=16 half

__device__ __forceinline__ uint32_t smem_u32(const void* p) {
    uint32_t a;
    asm("{ .reg .u64 t; cvta.to.shared.u64 t, %1; cvt.u32.u64 %0, t; }" : "=r"(a) : "l"(p));
    return a;
}
__device__ __forceinline__ void cp16(uint32_t dst, const void* src) {
    asm volatile("cp.async.cg.shared.global [%0], [%1], 16;" :: "r"(dst), "l"(src));
}
__device__ __forceinline__ void ldmx4(uint32_t* r, uint32_t addr) {
    asm volatile("ldmatrix.sync.aligned.m8n8.x4.shared.b16 {%0,%1,%2,%3}, [%4];"
                 : "=r"(r[0]), "=r"(r[1]), "=r"(r[2]), "=r"(r[3]) : "r"(addr));
}
__device__ __forceinline__ void mma16816(float* c, const uint32_t* a, const uint32_t* b) {
    asm volatile(
        "mma.sync.aligned.m16n8k16.row.col.f32.f16.f16.f32 "
        "{%0,%1,%2,%3}, {%4,%5,%6,%7}, {%8,%9}, {%0,%1,%2,%3};"
        : "+f"(c[0]), "+f"(c[1]), "+f"(c[2]), "+f"(c[3])
        : "r"(a[0]), "r"(a[1]), "r"(a[2]), "r"(a[3]), "r"(b[0]), "r"(b[1]));
}
__device__ __forceinline__ uint32_t pack2h(float v0, float v1) {
    __half2 h = __floats2half2_rn(v0, v1);
    return *(uint32_t*)&h;
}

// ------------------------------ GEMM ---------------------------------------
// mode 0: C = alpha * acc (fp32);  mode 1: fused qkv split epilogue
// Requires NC >= 3 (smallest caller NC = 4).
__global__ __launch_bounds__(256, 1)
void gemm2_kernel(const __half* __restrict__ Ah, const __half* __restrict__ Al,
                  const __half* __restrict__ Bh,
                  float* __restrict__ C,
                  int K, int lda, int ldb, int ldc,
                  long long sAo, long long sBo, long long sCo,
                  float alpha, int causal_skip, int causal_klim, int mode, int rev_y)
{
    const int by = rev_y ? (gridDim.y - 1 - blockIdx.y) : blockIdx.y;
    const int m0 = by * 128;
    const int n0 = blockIdx.x * 128;
    if (causal_skip && n0 > m0 + 127) return;

    const int bz = blockIdx.z;
    Ah += (long long)bz * sAo;  Al += (long long)bz * sAo;
    Bh += (long long)bz * sBo;
    C  += (long long)bz * sCo;

    int Keff = K;
    if (causal_klim) { int lim = m0 + 128; Keff = (lim < K) ? lim : K; }
    const int NC = Keff / 32;

    extern __shared__ char smem[];
    const uint32_t sb = smem_u32(smem);
    const int tid = threadIdx.x;
    const int wid = tid >> 5;
    const int lane = tid & 31;

    // stage loader: 3 tiles of [128 rows x 32 halfs]; 128r x 4 chunks = 512 ids
    auto load_stage = [&](int s, int c) {
        const uint32_t base = sb + s * STAGE_B;
        const int k0 = c * 32;
#pragma unroll
        for (int it = 0; it < 2; ++it) {
            const int id  = tid + it * 256;
            const int row = id >> 2;
            const int c16 = id & 3;
            const uint32_t so = (uint32_t)(row * SA + c16 * 8) * 2;
            const long long ga = (long long)(m0 + row) * lda + k0 + c16 * 8;
            const long long gb = (long long)(n0 + row) * ldb + k0 + c16 * 8;
            cp16(base + so,              Ah + ga);
            cp16(base + TILE_B + so,     Al + ga);
            cp16(base + 2 * TILE_B + so, Bh + gb);
        }
        asm volatile("cp.async.commit_group;" ::: "memory");
    };

    float acc[4][4][4];
#pragma unroll
    for (int i = 0; i < 4; ++i)
#pragma unroll
        for (int j = 0; j < 4; ++j)
#pragma unroll
            for (int q = 0; q < 4; ++q) acc[i][j][q] = 0.f;

    const int wm = (wid & 1) * 64;       // warp m offset (0/64)
    const int wn = (wid >> 1) * 32;      // warp n offset (0..96)
    const int gr = lane >> 3;
    const int rr = lane & 7;

    const uint32_t a_off = (uint32_t)((wm + (gr & 1) * 8 + rr) * SA + (gr >> 1) * 8) * 2;
    const uint32_t b_off = (uint32_t)((wn + (gr >> 1) * 8 + rr) * SA + (gr & 1) * 8) * 2;

    // two fragment buffer sets (compile-time selected)
    uint32_t fah0[4][4], fal0[4][4], fbh0[4][2];
    uint32_t fah1[4][4], fal1[4][4], fbh1[4][2];

    auto load_frags = [&](uint32_t st, uint32_t koff,
                          uint32_t (&fah)[4][4], uint32_t (&fal)[4][4],
                          uint32_t (&fbh)[4][2]) {
#pragma unroll
        for (int nt = 0; nt < 2; ++nt) {
            uint32_t r[4];
            ldmx4(r, st + 2 * TILE_B + b_off + koff + (uint32_t)(nt * 16 * SA) * 2);
            fbh[nt * 2 + 0][0] = r[0]; fbh[nt * 2 + 0][1] = r[1];
            fbh[nt * 2 + 1][0] = r[2]; fbh[nt * 2 + 1][1] = r[3];
        }
#pragma unroll
        for (int mi = 0; mi < 4; ++mi) {
            const uint32_t off = a_off + koff + (uint32_t)(mi * 16 * SA) * 2;
            ldmx4(fah[mi], st + off);
            ldmx4(fal[mi], st + TILE_B + off);
        }
    };
    auto mma_all = [&](uint32_t (&fah)[4][4], uint32_t (&fal)[4][4],
                       uint32_t (&fbh)[4][2]) {
#pragma unroll
        for (int mi = 0; mi < 4; ++mi) {
#pragma unroll
            for (int nj = 0; nj < 4; ++nj) mma16816(acc[mi][nj], fah[mi], fbh[nj]);
#pragma unroll
            for (int nj = 0; nj < 4; ++nj) mma16816(acc[mi][nj], fal[mi], fbh[nj]);
        }
    };

    // prologue: 3 stages in flight; frags for (chunk0, kk=0)
    load_stage(0, 0);
    load_stage(1, 1);
    load_stage(2, 2);
    asm volatile("cp.async.wait_group 2;" ::: "memory");
    __syncthreads();
    load_frags(sb, 0, fah0, fal0, fbh0);

    for (int c = 0; c < NC; ++c) {
        const uint32_t st = sb + (c % 3) * STAGE_B;

        // half 0: compute (c, kk=0) from set0; prefetch (c, kk=16) into set1
        load_frags(st, KOFF16, fah1, fal1, fbh1);
        mma_all(fah0, fal0, fbh0);

        // stage c fully read by this warp; make stage c+1 visible everywhere
        if (c + 2 < NC) asm volatile("cp.async.wait_group 1;" ::: "memory");
        else            asm volatile("cp.async.wait_group 0;" ::: "memory");
        __syncthreads();                       // reads of c done + c+1 visible
        if (c + 3 < NC) load_stage(c % 3, c + 3);
        if (c + 1 < NC)
            load_frags(sb + ((c + 1) % 3) * STAGE_B, 0, fah0, fal0, fbh0);

        // half 1: compute (c, kk=16) from set1
        mma_all(fah1, fal1, fbh1);
    }

    // ---- epilogue ----
    if (mode == 0) {
#pragma unroll
        for (int mi = 0; mi < 4; ++mi)
#pragma unroll
            for (int nj = 0; nj < 4; ++nj) {
                const int row = m0 + wm + mi * 16 + (lane >> 2);
                const int col = n0 + wn + nj * 8 + (lane & 3) * 2;
                float2 v0 = make_float2(alpha * acc[mi][nj][0], alpha * acc[mi][nj][1]);
                float2 v1 = make_float2(alpha * acc[mi][nj][2], alpha * acc[mi][nj][3]);
                *(float2*)(C + (long long)row * ldc + col)       = v0;
                *(float2*)(C + (long long)(row + 8) * ldc + col) = v1;
            }
    } else {
        const int seg = n0 >> 10;                      // 0=q 1=k 2=v
#pragma unroll
        for (int mi = 0; mi < 4; ++mi)
#pragma unroll
            for (int nj = 0; nj < 4; ++nj) {
                const int row = m0 + wm + mi * 16 + (lane >> 2);
                const int cc  = (n0 & 1023) + wn + nj * 8 + (lane & 3) * 2;
                const float v00 = acc[mi][nj][0], v01 = acc[mi][nj][1];
                const float v10 = acc[mi][nj][2], v11 = acc[mi][nj][3];
                const long long o0 = (long long)row * 1024 + cc;
                const long long o1 = (long long)(row + 8) * 1024 + cc;
                if (seg == 2) {
                    *(float2*)(g_vf + o0) = make_float2(v00, v01);
                    *(float2*)(g_vf + o1) = make_float2(v10, v11);
                } else if (seg == 1) {                 // k: single fp16
                    *(uint32_t*)(g_kh + o0) = pack2h(v00, v01);
                    *(uint32_t*)(g_kh + o1) = pack2h(v10, v11);
                } else {                               // q: fp16 hi + lo
                    __half h00 = __float2half_rn(v00), h01 = __float2half_rn(v01);
                    __half h10 = __float2half_rn(v10), h11 = __float2half_rn(v11);
                    __half2 p0; p0.x = h00; p0.y = h01;
                    __half2 p1; p1.x = h10; p1.y = h11;
                    *(uint32_t*)(g_qh + o0) = *(uint32_t*)&p0;
                    *(uint32_t*)(g_qh + o1) = *(uint32_t*)&p1;
                    *(uint32_t*)(g_ql + o0) = pack2h(v00 - __half2float(h00),
                                                     v01 - __half2float(h01));
                    *(uint32_t*)(g_ql + o1) = pack2h(v10 - __half2float(h10),
                                                     v11 - __half2float(h11));
                }
            }
    }
}

// --------------------- merged input split (x hi/lo, w single) --------------
#define X_N4 (8192LL * 1024 / 4)
#define W_N4 (3072LL * 1024 / 4)
__global__ void split_xw_kernel(const float* __restrict__ x, const float* __restrict__ w,
                                __half* __restrict__ xh, __half* __restrict__ xl,
                                __half* __restrict__ wh)
{
    long long i = (long long)blockIdx.x * blockDim.x + threadIdx.x;
    if (i < X_N4) {
        float4 v = *(const float4*)(x + i * 4);
        __half hv[4], lv[4];
#pragma unroll
        for (int q = 0; q < 4; ++q) {
            float f = (&v.x)[q];
            hv[q] = __float2half_rn(f);
            lv[q] = __float2half_rn(f - __half2float(hv[q]));
        }
        *(uint2*)(xh + i * 4) = *(uint2*)hv;
        *(uint2*)(xl + i * 4) = *(uint2*)lv;
    } else {
        long long o = i - X_N4;
        if (o >= W_N4) return;
        float4 v = *(const float4*)(w + o * 4);
        __half hv[4];
#pragma unroll
        for (int q = 0; q < 4; ++q) hv[q] = __float2half_rn((&v.x)[q]);
        *(uint2*)(wh + o * 4) = *(uint2*)hv;
    }
}

// V transpose (fp32 -> single fp16): vT[b][c][s] = vf[b*2048+s][c]
__global__ void vtrans_kernel(const float* __restrict__ vf, __half* __restrict__ vth)
{
    __shared__ float tile[32][33];
    const int s0 = blockIdx.x * 32, c0 = blockIdx.y * 32, b = blockIdx.z;
    const int tx = threadIdx.x, ty = threadIdx.y;
#pragma unroll
    for (int j = 0; j < 4; ++j) {
        const int s = s0 + ty + j * 8;
        tile[ty + j * 8][tx] = vf[(long long)(b * 2048 + s) * 1024 + c0 + tx];
    }
    __syncthreads();
#pragma unroll
    for (int j = 0; j < 4; ++j) {
        const int c = c0 + ty + j * 8;
        const long long o = ((long long)b * 1024 + c) * 2048 + s0 + tx;
        vth[o] = __float2half_rn(tile[tx][ty + j * 8]);
    }
}

// --------------------- causal softmax -> fp16 hi/lo ------------------------
__global__ void softmax_causal_kernel(const float* __restrict__ att,
                                      __half* __restrict__ ph,
                                      __half* __restrict__ pl)
{
    const int row = blockIdx.x;
    const int b = row >> 11, t = row & 2047;
    const float* p = att + ((long long)b * 2048 + t) * 2048;
    __half* hrow = ph + ((long long)b * 2048 + t) * 2048;
    __half* lrow = pl + ((long long)b * 2048 + t) * 2048;
    const int n = t + 1;
    const int zb = ((t >> 7) + 1) << 7;    // PV K-limit (128-aligned)
    const int tid = threadIdx.x;
    __shared__ float sbuf[8];

    float e[8];
    float m = -3.4e38f;
#pragma unroll
    for (int j = 0; j < 8; ++j) {
        const int i = tid + j * 256;
        e[j] = (i < n) ? p[i] : -3.4e38f;
        m = fmaxf(m, e[j]);
    }
#pragma unroll
    for (int o = 16; o > 0; o >>= 1) m = fmaxf(m, __shfl_xor_sync(0xffffffffu, m, o));
    if ((tid & 31) == 0) sbuf[tid >> 5] = m;
    __syncthreads();
    if (tid < 8) {
        float v = sbuf[tid];
#pragma unroll
        for (int o = 4; o > 0; o >>= 1) v = fmaxf(v, __shfl_xor_sync(0xffu, v, o));
        if (tid == 0) sbuf[0] = v;
    }
    __syncthreads();
    m = sbuf[0];
    __syncthreads();

    float s = 0.f;
#pragma unroll
    for (int j = 0; j < 8; ++j) {
        const int i = tid + j * 256;
        e[j] = (i < n) ? __expf(e[j] - m) : 0.f;
        s += e[j];
    }
#pragma unroll
    for (int o = 16; o > 0; o >>= 1) s += __shfl_xor_sync(0xffffffffu, s, o);
    if ((tid & 31) == 0) sbuf[tid >> 5] = s;
    __syncthreads();
    if (tid < 8) {
        float v = sbuf[tid];
#pragma unroll
        for (int o = 4; o > 0; o >>= 1) v += __shfl_xor_sync(0xffu, v, o);
        if (tid == 0) sbuf[0] = v;
    }
    __syncthreads();
    const float inv = 1.f / sbuf[0];

#pragma unroll
    for (int j = 0; j < 8; ++j) {
        const int i = tid + j * 256;
        if (i >= zb) break;
        const float v = e[j] * inv;
        const __half h = __float2half_rn(v);
        hrow[i] = h;
        lrow[i] = __float2half_rn(v - __half2float(h));
    }
}

// ---------------------------------------------------------------------------
extern "C" void kernel_launch(void* const* d_in, const int* in_sizes, int n_in,
                              void* d_out, int out_size)
{
    const float* x = (const float*)d_in[0];
    const float* w = (const float*)d_in[1];
    float* out = (float*)d_out;

    float *att, *vf;
    __half *xh, *xl, *wh, *qh, *ql, *kh, *vth, *phb, *plb;
    cudaGetSymbolAddress((void**)&att, g_att);
    cudaGetSymbolAddress((void**)&vf, g_vf);
    cudaGetSymbolAddress((void**)&xh, g_xh);   cudaGetSymbolAddress((void**)&xl, g_xl);
    cudaGetSymbolAddress((void**)&wh, g_wh);
    cudaGetSymbolAddress((void**)&qh, g_qh);   cudaGetSymbolAddress((void**)&ql, g_ql);
    cudaGetSymbolAddress((void**)&kh, g_kh);
    cudaGetSymbolAddress((void**)&vth, g_vth);
    cudaGetSymbolAddress((void**)&phb, g_ph);  cudaGetSymbolAddress((void**)&plb, g_pl);

    cudaFuncSetAttribute(gemm2_kernel, cudaFuncAttributeMaxDynamicSharedMemorySize,
                         GEMM_SMEM);

    // 0) split x (hi/lo) and w (single)
    {
        const long long total = X_N4 + W_N4;
        split_xw_kernel<<<(int)((total + 255) / 256), 256>>>(x, w, xh, xl, wh);
    }
    // 1) qkv = x @ w^T  (fused split epilogue)
    {
        dim3 grid(3072 / 128, 8192 / 128, 1);
        gemm2_kernel<<<grid, 256, GEMM_SMEM>>>(xh, xl, wh, nullptr,
                                               1024, 1024, 1024, 0,
                                               0, 0, 0, 1.0f, 0, 0, 1, 0);
    }
    // 2) transpose v -> fp16
    {
        dim3 grid(2048 / 32, 1024 / 32, 4);
        vtrans_kernel<<<grid, dim3(32, 8)>>>(vf, vth);
    }
    // 3) S = q k^T / 32  (causal tile skip; heavy rows first)  [profiled slot]
    {
        dim3 grid(2048 / 128, 2048 / 128, 4);
        gemm2_kernel<<<grid, 256, GEMM_SMEM>>>(qh, ql, kh, att,
                                               1024, 1024, 1024, 2048,
                                               2048LL * 1024, 2048LL * 1024, 2048LL * 2048,
                                               0.03125f, 1, 0, 0, 1);
    }
    // 4) P = softmax(S) -> fp16 hi/lo
    softmax_causal_kernel<<<4 * 2048, 256>>>(att, phb, plb);

    // 5) y = P @ V  (V^T K-major, causal K-limit; heavy rows first)
    {
        dim3 grid(1024 / 128, 2048 / 128, 4);
        gemm2_kernel<<<grid, 256, GEMM_SMEM>>>(phb, plb, vth, out,
                                               2048, 2048, 2048, 1024,
                                               2048LL * 2048, 1024LL * 2048, 2048LL * 1024,
                                               1.0f, 0, 1, 0, 1);
    }
}